// round 2
// baseline (speedup 1.0000x reference)
#include <cuda_runtime.h>
#include <cuda_fp16.h>
#include <math.h>

// Problem constants
#define B_TOTAL 512
#define T_STEPS 1024
#define F_IN    32
#define HID     128
#define BC      4                 // batch rows per block
#define NBLK    (B_TOTAL / BC)    // 128 blocks
#define NTHR    256

// Packed weight scratch, fp16, k-major, gate-interleaved: idx = k*512 + 4*j + gate
__device__ __half g_W0h[160 * 512];  // layer0: k in [0,32)=Wih0, [32,160)=Whh0
__device__ __half g_W1h[256 * 512];  // layer1: k in [0,128)=Wih1, [128,256)=Whh1
__device__ float  g_B0[512];         // bih0+bhh0, gate-interleaved
__device__ float  g_B1[512];

__global__ void pack_kernel(const float* __restrict__ Wih0, const float* __restrict__ Whh0,
                            const float* __restrict__ bih0, const float* __restrict__ bhh0,
                            const float* __restrict__ Wih1, const float* __restrict__ Whh1,
                            const float* __restrict__ bih1, const float* __restrict__ bhh1)
{
    int idx = blockIdx.x * blockDim.x + threadIdx.x;
    if (idx < 160 * 512) {
        int k = idx >> 9, c = idx & 511;
        int j = c >> 2, g = c & 3, row = g * HID + j;
        float w = (k < F_IN) ? Wih0[row * F_IN + k] : Whh0[row * HID + (k - F_IN)];
        g_W0h[idx] = __float2half_rn(w);
    }
    if (idx < 256 * 512) {
        int k = idx >> 9, c = idx & 511;
        int j = c >> 2, g = c & 3, row = g * HID + j;
        float w = (k < HID) ? Wih1[row * HID + k] : Whh1[row * HID + (k - HID)];
        g_W1h[idx] = __float2half_rn(w);
    }
    if (idx < 512) {
        int j = idx >> 2, g = idx & 3, row = g * HID + j;
        g_B0[idx] = bih0[row] + bhh0[row];
        g_B1[idx] = bih1[row] + bhh1[row];
    }
}

// ---- packed f32x2 helpers ----
__device__ __forceinline__ unsigned long long pk2(float lo, float hi) {
    unsigned long long r;
    asm("mov.b64 %0, {%1, %2};" : "=l"(r) : "r"(__float_as_uint(lo)), "r"(__float_as_uint(hi)));
    return r;
}
__device__ __forceinline__ void upk2(unsigned long long v, float& lo, float& hi) {
    unsigned int a, b;
    asm("mov.b64 {%0, %1}, %2;" : "=r"(a), "=r"(b) : "l"(v));
    lo = __uint_as_float(a); hi = __uint_as_float(b);
}
__device__ __forceinline__ void fma2(unsigned long long& d, unsigned long long a, unsigned long long b) {
    asm("fma.rn.f32x2 %0, %1, %2, %0;" : "+l"(d) : "l"(a), "l"(b));
}

__device__ __forceinline__ float sigf(float x) {
    return 1.0f / (1.0f + __expf(-x));
}
__device__ __forceinline__ float tanhfast(float x) {
    float cx = fminf(fmaxf(x, -15.f), 15.f);
    float e  = __expf(-2.f * cx);
    return (1.f - e) / (1.f + e);
}

__global__ __launch_bounds__(NTHR)
void lstm_main(const float* __restrict__ x,
               const float* __restrict__ ln_g, const float* __restrict__ ln_b,
               const float* __restrict__ W1,   const float* __restrict__ b1,
               const float* __restrict__ W2,   const float* __restrict__ b2,
               float* __restrict__ out)
{
    __shared__ float a0[BC][160];   // [0:32) = x_t, [32:160) = h0 state
    __shared__ float a1[BC][256];   // [0:128) = h0_new (layer1 input), [128:256) = h1 state
    __shared__ float red[BC][64];
    __shared__ float mv[BC][2];

    const int bid = blockIdx.x;
    const int tid = threadIdx.x;
    const int rh  = tid >> 7;       // 0..1 -> rows {2rh, 2rh+1}
    const int j   = tid & 127;      // hidden column
    const int r0  = rh * 2;

    for (int i = tid; i < BC * 160; i += NTHR) (&a0[0][0])[i] = 0.f;
    for (int i = tid; i < BC * 256; i += NTHR) (&a1[0][0])[i] = 0.f;

    // fp16 weights viewed as uint2 (4 halves = gates i,f,g,o of column j at row k)
    const uint2* __restrict__ W0v = reinterpret_cast<const uint2*>(g_W0h);
    const uint2* __restrict__ W1v = reinterpret_cast<const uint2*>(g_W1h);
    const float4 b0v = reinterpret_cast<const float4*>(g_B0)[j];
    const float4 b1v = reinterpret_cast<const float4*>(g_B1)[j];

    float c0a = 0.f, c0b = 0.f, c1a = 0.f, c1b = 0.f;

    const float* xbase = x + (size_t)(bid * BC) * T_STEPS * F_IN;

    for (int t = 0; t < T_STEPS; ++t) {
        // stage x_t (this barrier also publishes last step's h1 writes)
        if (tid < 128) {
            int r = tid >> 5, k = tid & 31;
            a0[r][k] = xbase[(size_t)r * T_STEPS * F_IN + t * F_IN + k];
        }
        __syncthreads();

        // ---------------- layer 0: gates = [x_t, h0] @ W0 ----------------
        // packed accumulators: (i,f) and (g,o) per row
        unsigned long long aif = 0ULL, ago = 0ULL, bif = 0ULL, bgo = 0ULL;
        #pragma unroll 4
        for (int k4 = 0; k4 < 40; ++k4) {
            float4 av4 = *reinterpret_cast<const float4*>(&a0[r0][k4 * 4]);
            float4 bv4 = *reinterpret_cast<const float4*>(&a0[r0 + 1][k4 * 4]);
            float avv[4] = {av4.x, av4.y, av4.z, av4.w};
            float bvv[4] = {bv4.x, bv4.y, bv4.z, bv4.w};
            #pragma unroll
            for (int q = 0; q < 4; ++q) {
                uint2 wv = W0v[(k4 * 4 + q) * 128 + j];
                float2 wif = __half22float2(*reinterpret_cast<const __half2*>(&wv.x));
                float2 wgo = __half22float2(*reinterpret_cast<const __half2*>(&wv.y));
                unsigned long long wifp = pk2(wif.x, wif.y);
                unsigned long long wgop = pk2(wgo.x, wgo.y);
                unsigned long long apA = pk2(avv[q], avv[q]);
                unsigned long long apB = pk2(bvv[q], bvv[q]);
                fma2(aif, wifp, apA); fma2(ago, wgop, apA);
                fma2(bif, wifp, apB); fma2(bgo, wgop, apB);
            }
        }
        __syncthreads();   // all reads of a0 h-region done before overwrite
        {
            float ai, af, ag, ao, bi, bf, bg, bo;
            upk2(aif, ai, af); upk2(ago, ag, ao);
            upk2(bif, bi, bf); upk2(bgo, bg, bo);

            float ig = sigf(ai + b0v.x), fg = sigf(af + b0v.y);
            float gg = tanhfast(ag + b0v.z), og = sigf(ao + b0v.w);
            c0a = fg * c0a + ig * gg;
            float h = og * tanhfast(c0a);
            a0[r0][32 + j] = h;  a1[r0][j] = h;

            ig = sigf(bi + b0v.x); fg = sigf(bf + b0v.y);
            gg = tanhfast(bg + b0v.z); og = sigf(bo + b0v.w);
            c0b = fg * c0b + ig * gg;
            h = og * tanhfast(c0b);
            a0[r0 + 1][32 + j] = h;  a1[r0 + 1][j] = h;
        }
        __syncthreads();   // publish h0_new before layer1 reads a1

        // ---------------- layer 1: gates = [h0_new, h1] @ W1 ----------------
        aif = 0ULL; ago = 0ULL; bif = 0ULL; bgo = 0ULL;
        #pragma unroll 4
        for (int k4 = 0; k4 < 64; ++k4) {
            float4 av4 = *reinterpret_cast<const float4*>(&a1[r0][k4 * 4]);
            float4 bv4 = *reinterpret_cast<const float4*>(&a1[r0 + 1][k4 * 4]);
            float avv[4] = {av4.x, av4.y, av4.z, av4.w};
            float bvv[4] = {bv4.x, bv4.y, bv4.z, bv4.w};
            #pragma unroll
            for (int q = 0; q < 4; ++q) {
                uint2 wv = W1v[(k4 * 4 + q) * 128 + j];
                float2 wif = __half22float2(*reinterpret_cast<const __half2*>(&wv.x));
                float2 wgo = __half22float2(*reinterpret_cast<const __half2*>(&wv.y));
                unsigned long long wifp = pk2(wif.x, wif.y);
                unsigned long long wgop = pk2(wgo.x, wgo.y);
                unsigned long long apA = pk2(avv[q], avv[q]);
                unsigned long long apB = pk2(bvv[q], bvv[q]);
                fma2(aif, wifp, apA); fma2(ago, wgop, apA);
                fma2(bif, wifp, apB); fma2(bgo, wgop, apB);
            }
        }
        __syncthreads();   // all reads of a1 h1-region done before overwrite
        {
            float ai, af, ag, ao, bi, bf, bg, bo;
            upk2(aif, ai, af); upk2(ago, ag, ao);
            upk2(bif, bi, bf); upk2(bgo, bg, bo);

            float ig = sigf(ai + b1v.x), fg = sigf(af + b1v.y);
            float gg = tanhfast(ag + b1v.z), og = sigf(ao + b1v.w);
            c1a = fg * c1a + ig * gg;
            a1[r0][128 + j] = og * tanhfast(c1a);

            ig = sigf(bi + b1v.x); fg = sigf(bf + b1v.y);
            gg = tanhfast(bg + b1v.z); og = sigf(bo + b1v.w);
            c1b = fg * c1b + ig * gg;
            a1[r0 + 1][128 + j] = og * tanhfast(c1b);
        }
        // next iteration's staging __syncthreads publishes h1
    }
    __syncthreads();

    // ---------------- head: LayerNorm -> Linear(64) -> ReLU -> Linear(1) -> sigmoid ----
    if (tid < BC) {
        int r = tid;
        float s = 0.f;
        for (int k = 0; k < HID; ++k) s += a1[r][128 + k];
        float mu = s * (1.f / HID);
        float v = 0.f;
        for (int k = 0; k < HID; ++k) { float d = a1[r][128 + k] - mu; v += d * d; }
        v *= (1.f / HID);
        mv[r][0] = mu;
        mv[r][1] = rsqrtf(v + 1e-5f);
    }
    __syncthreads();
    {
        int r = tid >> 6, u = tid & 63;
        float mu = mv[r][0], rs = mv[r][1];
        float acc = b1[u];
        for (int k = 0; k < HID; ++k) {
            float lnv = (a1[r][128 + k] - mu) * rs * ln_g[k] + ln_b[k];
            acc += lnv * W1[u * HID + k];
        }
        red[r][u] = fmaxf(acc, 0.f);
    }
    __syncthreads();
    if (tid < BC) {
        int r = tid;
        float y = b2[0];
        for (int u = 0; u < 64; ++u) y += red[r][u] * W2[u];
        out[bid * BC + r] = sigf(y);
    }
}

extern "C" void kernel_launch(void* const* d_in, const int* in_sizes, int n_in,
                              void* d_out, int out_size)
{
    const float* x    = (const float*)d_in[0];
    const float* Wih0 = (const float*)d_in[1];
    const float* Whh0 = (const float*)d_in[2];
    const float* bih0 = (const float*)d_in[3];
    const float* bhh0 = (const float*)d_in[4];
    const float* Wih1 = (const float*)d_in[5];
    const float* Whh1 = (const float*)d_in[6];
    const float* bih1 = (const float*)d_in[7];
    const float* bhh1 = (const float*)d_in[8];
    const float* ln_g = (const float*)d_in[9];
    const float* ln_b = (const float*)d_in[10];
    const float* W1   = (const float*)d_in[11];
    const float* b1   = (const float*)d_in[12];
    const float* W2   = (const float*)d_in[13];
    const float* b2   = (const float*)d_in[14];
    float* out = (float*)d_out;

    pack_kernel<<<512, 256>>>(Wih0, Whh0, bih0, bhh0, Wih1, Whh1, bih1, bhh1);
    lstm_main<<<NBLK, NTHR>>>(x, ln_g, ln_b, W1, b1, W2, b2, out);
}